// round 1
// baseline (speedup 1.0000x reference)
#include <cuda_runtime.h>
#include <math.h>

#define B 16
#define N 32
#define C 512
#define FEAT 224

// Per-batch output row length: 512*(784+196+49) = 526848
#define HW0 784
#define HW1 196
#define HW2 49
#define OUT_ROW (C*(HW0+HW1+HW2))
#define OUT_OFF1 (C*HW0)         // 401408
#define OUT_OFF2 (C*(HW0+HW1))   // 501760

// ---------------- scratch (no allocations allowed) ----------------
__device__ float g_att0[B * HW0];
__device__ float g_att1[B * HW1];
__device__ float g_att2[B * HW2];
__device__ float g_logits[3 * B * C];
__device__ float g_weights[3 * B * C];

// ---------------- K1: conf map + sigmoid + 3-level avgpool ----------------
// grid = B blocks, 784 threads. Thread t owns one 8x8 pixel tile (one att0 cell).
__global__ void conf_att_kernel(const float* __restrict__ confs,
                                const float* __restrict__ boxes) {
    int b = blockIdx.x;
    __shared__ float sconf[N];
    __shared__ int sx1[N], sy1[N], sx2[N], sy2[N];
    __shared__ float sum28[HW0];

    int t = threadIdx.x;
    if (t < N) {
        sconf[t] = confs[b * N + t];
        const float* bx = boxes + (b * N + t) * 4;
        sx1[t] = (int)floorf(bx[0] * (float)FEAT);
        sy1[t] = (int)floorf(bx[1] * (float)FEAT);
        sx2[t] = (int)floorf(bx[2] * (float)FEAT);
        sy2[t] = (int)floorf(bx[3] * (float)FEAT);
    }
    __syncthreads();

    int cy = t / 28, cx = t % 28;
    int py0 = cy * 8, px0 = cx * 8;

    float tsum = 0.f;
    for (int ry = 0; ry < 8; ry++) {
        int y = py0 + ry;
        float v[8];
#pragma unroll
        for (int j = 0; j < 8; j++) v[j] = 0.f;
        for (int n = 0; n < N; n++) {
            if (y >= sy1[n] && y < sy2[n]) {
                float cf = sconf[n];
                int xa = sx1[n] - px0, xb = sx2[n] - px0;
#pragma unroll
                for (int j = 0; j < 8; j++)
                    if (j >= xa && j < xb) v[j] += cf;
            }
        }
#pragma unroll
        for (int j = 0; j < 8; j++)
            tsum += 1.f / (1.f + expf(-v[j]));
    }
    sum28[t] = tsum;
    g_att0[b * HW0 + t] = tsum * (1.f / 64.f);
    __syncthreads();

    if (t < HW1) {
        int ay = t / 14, ax = t % 14;
        float s = sum28[(2 * ay) * 28 + 2 * ax] + sum28[(2 * ay) * 28 + 2 * ax + 1] +
                  sum28[(2 * ay + 1) * 28 + 2 * ax] + sum28[(2 * ay + 1) * 28 + 2 * ax + 1];
        g_att1[b * HW1 + t] = s * (1.f / 256.f);
    }
    if (t < HW2) {
        int ay = t / 7, ax = t % 7;
        float s = 0.f;
#pragma unroll
        for (int i = 0; i < 4; i++)
#pragma unroll
            for (int j = 0; j < 4; j++)
                s += sum28[(4 * ay + i) * 28 + 4 * ax + j];
        g_att2[b * HW2 + t] = s * (1.f / 1024.f);
    }
}

// ---------------- K2: logits[l][b][c] = dot(feat[b,c,:], att[b,:]) ----------------
// grid = (C/8, B, 3), 256 threads = 8 warps; each warp does one c.
__global__ void logits_kernel(const float* __restrict__ f0,
                              const float* __restrict__ f1,
                              const float* __restrict__ f2) {
    int l = blockIdx.z, b = blockIdx.y;
    const float* feat;
    const float* att;
    int HW;
    if (l == 0)      { feat = f0; att = g_att0; HW = HW0; }
    else if (l == 1) { feat = f1; att = g_att1; HW = HW1; }
    else             { feat = f2; att = g_att2; HW = HW2; }

    __shared__ float satt[HW0];
    for (int i = threadIdx.x; i < HW; i += blockDim.x) satt[i] = att[b * HW + i];
    __syncthreads();

    int warp = threadIdx.x >> 5, lane = threadIdx.x & 31;
    int c = blockIdx.x * 8 + warp;
    const float* fp = feat + ((size_t)(b * C + c)) * HW;
    float acc = 0.f;
    for (int i = lane; i < HW; i += 32) acc = fmaf(fp[i], satt[i], acc);
#pragma unroll
    for (int o = 16; o > 0; o >>= 1) acc += __shfl_xor_sync(0xffffffffu, acc, o);
    if (lane == 0) g_logits[(l * B + b) * C + c] = acc;
}

// ---------------- K3: softmax over C per (level, b) ----------------
// grid = 3*B blocks, 512 threads (t == c)
__global__ void softmax_kernel() {
    int lb = blockIdx.x;
    int t = threadIdx.x;
    float x = g_logits[lb * C + t];

    __shared__ float red[16];
    __shared__ float smax, ssum;

    float m = x;
#pragma unroll
    for (int o = 16; o > 0; o >>= 1) m = fmaxf(m, __shfl_xor_sync(0xffffffffu, m, o));
    if ((t & 31) == 0) red[t >> 5] = m;
    __syncthreads();
    if (t == 0) {
        float mm = red[0];
#pragma unroll
        for (int i = 1; i < 16; i++) mm = fmaxf(mm, red[i]);
        smax = mm;
    }
    __syncthreads();

    float e = expf(x - smax);
    float s = e;
#pragma unroll
    for (int o = 16; o > 0; o >>= 1) s += __shfl_xor_sync(0xffffffffu, s, o);
    if ((t & 31) == 0) red[t >> 5] = s;
    __syncthreads();
    if (t == 0) {
        float ss = 0.f;
#pragma unroll
        for (int i = 0; i < 16; i++) ss += red[i];
        ssum = ss;
    }
    __syncthreads();

    g_weights[lb * C + t] = e / ssum;
}

// ---------------- K4: out = feat * w, vectorized float4 (HW % 4 == 0) ----------------
template <int HW, int LVL, int OUTBASE>
__global__ void scale_vec_kernel(const float* __restrict__ feat, float* __restrict__ out) {
    constexpr int HW4 = HW / 4;
    int gid = blockIdx.x * blockDim.x + threadIdx.x;
    constexpr int total = B * C * HW4;
    if (gid >= total) return;
    int b = gid / (C * HW4);
    int rem = gid - b * (C * HW4);
    int c = rem / HW4;
    float w = g_weights[(LVL * B + b) * C + c];
    float4 v = ((const float4*)feat)[gid];
    v.x *= w; v.y *= w; v.z *= w; v.w *= w;
    ((float4*)(out + (size_t)b * OUT_ROW + OUTBASE))[rem] = v;
}

// Level 2 (HW=49, odd) scalar path
__global__ void scale_l2_kernel(const float* __restrict__ feat, float* __restrict__ out) {
    int gid = blockIdx.x * blockDim.x + threadIdx.x;
    constexpr int total = B * C * HW2;
    if (gid >= total) return;
    int b = gid / (C * HW2);
    int rem = gid - b * (C * HW2);
    int c = rem / HW2;
    float w = g_weights[(2 * B + b) * C + c];
    out[(size_t)b * OUT_ROW + OUT_OFF2 + rem] = feat[gid] * w;
}

extern "C" void kernel_launch(void* const* d_in, const int* in_sizes, int n_in,
                              void* d_out, int out_size) {
    const float* confs = (const float*)d_in[0];
    const float* boxes = (const float*)d_in[1];
    const float* f0 = (const float*)d_in[2];
    const float* f1 = (const float*)d_in[3];
    const float* f2 = (const float*)d_in[4];
    float* out = (float*)d_out;

    conf_att_kernel<<<B, HW0>>>(confs, boxes);
    logits_kernel<<<dim3(C / 8, B, 3), 256>>>(f0, f1, f2);
    softmax_kernel<<<3 * B, C>>>();

    {
        constexpr int tot0 = B * C * (HW0 / 4);
        scale_vec_kernel<HW0, 0, 0><<<(tot0 + 255) / 256, 256>>>(f0, out);
    }
    {
        constexpr int tot1 = B * C * (HW1 / 4);
        scale_vec_kernel<HW1, 1, OUT_OFF1><<<(tot1 + 255) / 256, 256>>>(f1, out);
    }
    {
        constexpr int tot2 = B * C * HW2;
        scale_l2_kernel<<<(tot2 + 255) / 256, 256>>>(f2, out);
    }
}